// round 1
// baseline (speedup 1.0000x reference)
#include <cuda_runtime.h>
#include <cuda_bf16.h>
#include <math.h>

#define NN 4096
#define HH 256
#define EE 65536

// ---------------- device scratch (no allocations allowed) ----------------
__device__ float g_h[NN * HH];
__device__ float g_xlin[NN * HH];
__device__ float g_qkv[NN * 3 * HH];
__device__ float g_attn[NN * HH];
__device__ float g_proj[NN * HH];
__device__ float g_agg[NN * HH];
__device__ float g_out[NN * HH];
__device__ float g_ffn[NN * 2 * HH];
__device__ float g_hid[NN * HH];
__device__ float g_deg[NN];
__device__ float g_dinv[NN];

// ---------------- generic SGEMM: C = act(A @ W^T + bias + add) ----------------
// A: [M,K] row-major, W: [N,K] row-major (torch Linear weight), C: [M,N]
#define BM 64
#define BN 64
#define BK 16

__global__ void sgemm(const float* __restrict__ A, const float* __restrict__ W,
                      const float* __restrict__ bias, const float* __restrict__ add,
                      float* __restrict__ C, int M, int Nn, int K, int relu) {
    __shared__ float As[BK][BM + 4];
    __shared__ float Ws[BK][BN + 4];
    int tx = threadIdx.x, ty = threadIdx.y;
    int tid = ty * 16 + tx;
    int m0 = blockIdx.y * BM, n0 = blockIdx.x * BN;

    float acc[4][4];
#pragma unroll
    for (int i = 0; i < 4; i++)
#pragma unroll
        for (int j = 0; j < 4; j++) acc[i][j] = 0.f;

    int lr = tid >> 2;          // row 0..63
    int lk = (tid & 3) * 4;     // k offset 0,4,8,12

    for (int k0 = 0; k0 < K; k0 += BK) {
        float4 av = *(const float4*)&A[(long)(m0 + lr) * K + k0 + lk];
        float4 wv = *(const float4*)&W[(long)(n0 + lr) * K + k0 + lk];
        As[lk + 0][lr] = av.x; As[lk + 1][lr] = av.y;
        As[lk + 2][lr] = av.z; As[lk + 3][lr] = av.w;
        Ws[lk + 0][lr] = wv.x; Ws[lk + 1][lr] = wv.y;
        Ws[lk + 2][lr] = wv.z; Ws[lk + 3][lr] = wv.w;
        __syncthreads();
#pragma unroll
        for (int kk = 0; kk < BK; kk++) {
            float4 a = *(const float4*)&As[kk][ty * 4];
            float4 b = *(const float4*)&Ws[kk][tx * 4];
            float ar[4] = {a.x, a.y, a.z, a.w};
            float br[4] = {b.x, b.y, b.z, b.w};
#pragma unroll
            for (int i = 0; i < 4; i++)
#pragma unroll
                for (int j = 0; j < 4; j++) acc[i][j] += ar[i] * br[j];
        }
        __syncthreads();
    }

#pragma unroll
    for (int i = 0; i < 4; i++) {
        int m = m0 + ty * 4 + i;
#pragma unroll
        for (int j = 0; j < 4; j++) {
            int n = n0 + tx * 4 + j;
            float c = acc[i][j];
            if (bias) c += bias[n];
            if (add)  c += add[(long)m * Nn + n];
            if (relu) c = fmaxf(c, 0.f);
            C[(long)m * Nn + n] = c;
        }
    }
}

// ---------------- flash attention (fp32, online softmax) ----------------
// qkv: [N, 768]   q=cols[0:256) k=[256:512) v=[512:768), head h = 64-ch slice
#define FBM 64
#define FBN 32
#define FD  64

__global__ void flash_attn(const float* __restrict__ qkv, float* __restrict__ out, int n) {
    __shared__ float Qs[FBM][FD + 1];
    __shared__ float Ks[FBN][FD + 1];
    __shared__ float Vs[FBN][FD + 4];
    __shared__ float Ps[FBM][FBN + 1];
    int tx = threadIdx.x, ty = threadIdx.y;
    int tid = ty * 16 + tx;
    int q0 = blockIdx.x * FBM;
    int head = blockIdx.y;
    const int C3 = 3 * HH;

    for (int l = tid; l < FBM * FD; l += 256) {
        int r = l >> 6, d = l & 63;
        Qs[r][d] = qkv[(long)(q0 + r) * C3 + head * 64 + d] * 0.125f;
    }

    float m[4], lsum[4], acc[4][4];
#pragma unroll
    for (int i = 0; i < 4; i++) {
        m[i] = -1e30f; lsum[i] = 0.f;
#pragma unroll
        for (int j = 0; j < 4; j++) acc[i][j] = 0.f;
    }
    __syncthreads();

    for (int k0 = 0; k0 < n; k0 += FBN) {
        for (int l = tid; l < FBN * FD; l += 256) {
            int r = l >> 6, d = l & 63;
            Ks[r][d] = qkv[(long)(k0 + r) * C3 + HH + head * 64 + d];
            Vs[r][d] = qkv[(long)(k0 + r) * C3 + 2 * HH + head * 64 + d];
        }
        __syncthreads();

        // S = Q K^T  (rows ty*4+i, key cols tx*2+{0,1})
        float s[4][2];
#pragma unroll
        for (int i = 0; i < 4; i++) { s[i][0] = 0.f; s[i][1] = 0.f; }
#pragma unroll
        for (int d = 0; d < FD; d++) {
            float b0 = Ks[tx * 2 + 0][d];
            float b1 = Ks[tx * 2 + 1][d];
#pragma unroll
            for (int i = 0; i < 4; i++) {
                float a = Qs[ty * 4 + i][d];
                s[i][0] += a * b0;
                s[i][1] += a * b1;
            }
        }

        // online softmax update per owned row
#pragma unroll
        for (int i = 0; i < 4; i++) {
            float mx = fmaxf(s[i][0], s[i][1]);
#pragma unroll
            for (int o = 8; o > 0; o >>= 1) mx = fmaxf(mx, __shfl_xor_sync(0xffffffffu, mx, o));
            float mnew = fmaxf(m[i], mx);
            float p0 = __expf(s[i][0] - mnew);
            float p1 = __expf(s[i][1] - mnew);
            Ps[ty * 4 + i][tx * 2 + 0] = p0;
            Ps[ty * 4 + i][tx * 2 + 1] = p1;
            float rs = p0 + p1;
#pragma unroll
            for (int o = 8; o > 0; o >>= 1) rs += __shfl_xor_sync(0xffffffffu, rs, o);
            float scale = __expf(m[i] - mnew);
            lsum[i] = lsum[i] * scale + rs;
            m[i] = mnew;
#pragma unroll
            for (int j = 0; j < 4; j++) acc[i][j] *= scale;
        }
        __syncthreads();

        // O += P V   (d cols tx*4+j)
#pragma unroll
        for (int kk = 0; kk < FBN; kk++) {
            float4 v = *(const float4*)&Vs[kk][tx * 4];
            float vr[4] = {v.x, v.y, v.z, v.w};
#pragma unroll
            for (int i = 0; i < 4; i++) {
                float p = Ps[ty * 4 + i][kk];
#pragma unroll
                for (int j = 0; j < 4; j++) acc[i][j] += p * vr[j];
            }
        }
        __syncthreads();
    }

#pragma unroll
    for (int i = 0; i < 4; i++) {
        float inv = 1.f / lsum[i];
#pragma unroll
        for (int j = 0; j < 4; j++)
            out[(long)(q0 + ty * 4 + i) * HH + head * 64 + tx * 4 + j] = acc[i][j] * inv;
    }
}

// ---------------- GCN helpers ----------------
__global__ void deg_init(float* deg, int n) {
    int i = blockIdx.x * blockDim.x + threadIdx.x;
    if (i < n) deg[i] = 1.f;  // self loop
}
__global__ void deg_count(const int* __restrict__ dst, float* deg, int e) {
    int i = blockIdx.x * blockDim.x + threadIdx.x;
    if (i < e) atomicAdd(&deg[dst[i]], 1.f);
}
__global__ void dinv_kernel(const float* __restrict__ deg, float* dinv, int n) {
    int i = blockIdx.x * blockDim.x + threadIdx.x;
    if (i < n) dinv[i] = rsqrtf(deg[i]);
}

// one warp per edge: agg[dst] += xlin[src] * dinv[src]*dinv[dst]
__global__ void gcn_scatter(const int* __restrict__ src, const int* __restrict__ dst,
                            const float* __restrict__ dinv, const float* __restrict__ xlin,
                            float* __restrict__ agg, int e) {
    int w = (blockIdx.x * blockDim.x + threadIdx.x) >> 5;
    int lane = threadIdx.x & 31;
    if (w >= e) return;
    int s = src[w], d = dst[w];
    float coef = dinv[s] * dinv[d];
    const float* xs = xlin + (long)s * HH;
    float* ad = agg + (long)d * HH;
#pragma unroll
    for (int k = 0; k < HH / 32; k++)
        atomicAdd(&ad[lane + 32 * k], xs[lane + 32 * k] * coef);
}

// out = agg + xlin*dinv^2 (self loop) + gcn_b + proj + 2*h   (= h1 + h2 of GPSConv)
__global__ void combine(const float* __restrict__ agg, const float* __restrict__ xlin,
                        const float* __restrict__ dinv, const float* __restrict__ gcn_b,
                        const float* __restrict__ proj, const float* __restrict__ h,
                        float* __restrict__ out, int total) {
    int idx = blockIdx.x * blockDim.x + threadIdx.x;
    if (idx >= total) return;
    int i = idx >> 8, c = idx & 255;
    float dv = dinv[i];
    out[idx] = agg[idx] + xlin[idx] * dv * dv + gcn_b[c] + proj[idx] + 2.f * h[idx];
}

__global__ void symmetrize(float* __restrict__ o, int n) {
    long idx = (long)blockIdx.x * blockDim.x + threadIdx.x;
    if (idx >= (long)n * n) return;
    int i = (int)(idx / n), j = (int)(idx % n);
    if (i < j) {
        long t = (long)j * n + i;
        float v = 0.5f * (o[idx] + o[t]);
        o[idx] = v;
        o[t] = v;
    }
}

// ---------------- launch ----------------
extern "C" void kernel_launch(void* const* d_in, const int* in_sizes, int n_in,
                              void* d_out, int out_size) {
    const float* x      = (const float*)d_in[0];
    const int*   ei     = (const int*)d_in[1];
    const float* pre_w  = (const float*)d_in[2];
    const float* pre_b  = (const float*)d_in[3];
    const float* mlp_w1 = (const float*)d_in[24];
    const float* mlp_b1 = (const float*)d_in[25];
    const float* mlp_w2 = (const float*)d_in[26];
    const float* mlp_b2 = (const float*)d_in[27];

    float *h, *xlin, *qkv, *attn, *proj, *agg, *outb, *ffn, *hid, *deg, *dinv;
    cudaGetSymbolAddress((void**)&h,    g_h);
    cudaGetSymbolAddress((void**)&xlin, g_xlin);
    cudaGetSymbolAddress((void**)&qkv,  g_qkv);
    cudaGetSymbolAddress((void**)&attn, g_attn);
    cudaGetSymbolAddress((void**)&proj, g_proj);
    cudaGetSymbolAddress((void**)&agg,  g_agg);
    cudaGetSymbolAddress((void**)&outb, g_out);
    cudaGetSymbolAddress((void**)&ffn,  g_ffn);
    cudaGetSymbolAddress((void**)&hid,  g_hid);
    cudaGetSymbolAddress((void**)&deg,  g_deg);
    cudaGetSymbolAddress((void**)&dinv, g_dinv);

    dim3 tb(16, 16);

    // degree / normalization (shared by both layers)
    deg_init<<<(NN + 255) / 256, 256>>>(deg, NN);
    deg_count<<<(EE + 255) / 256, 256>>>(ei + EE, deg, EE);
    dinv_kernel<<<(NN + 255) / 256, 256>>>(deg, dinv, NN);

    // pre: h = relu(x @ pre_w^T + pre_b)
    sgemm<<<dim3(HH / BN, NN / BM), tb>>>(x, pre_w, pre_b, nullptr, h, NN, HH, 128, 1);

    for (int L = 0; L < 2; L++) {
        int base = 4 + L * 10;
        const float* gcn_w  = (const float*)d_in[base + 0];
        const float* gcn_b  = (const float*)d_in[base + 1];
        const float* in_w   = (const float*)d_in[base + 2];
        const float* in_b   = (const float*)d_in[base + 3];
        const float* out_w  = (const float*)d_in[base + 4];
        const float* out_b  = (const float*)d_in[base + 5];
        const float* ffn_w1 = (const float*)d_in[base + 6];
        const float* ffn_b1 = (const float*)d_in[base + 7];
        const float* ffn_w2 = (const float*)d_in[base + 8];
        const float* ffn_b2 = (const float*)d_in[base + 9];

        // GCN linear (bias applied in combine)
        sgemm<<<dim3(HH / BN, NN / BM), tb>>>(h, gcn_w, nullptr, nullptr, xlin, NN, HH, HH, 0);
        // attention qkv
        sgemm<<<dim3(3 * HH / BN, NN / BM), tb>>>(h, in_w, in_b, nullptr, qkv, NN, 3 * HH, HH, 0);
        flash_attn<<<dim3(NN / FBM, 4), tb>>>(qkv, attn, NN);
        // out projection (+bias)
        sgemm<<<dim3(HH / BN, NN / BM), tb>>>(attn, out_w, out_b, nullptr, proj, NN, HH, HH, 0);
        // GCN aggregation
        cudaMemsetAsync(agg, 0, (size_t)NN * HH * sizeof(float));
        gcn_scatter<<<(EE * 32) / 256, 256>>>(ei, ei + EE, dinv, xlin, agg, EE);
        // out = h1 + h2
        combine<<<(NN * HH) / 256, 256>>>(agg, xlin, dinv, gcn_b, proj, h, outb, NN * HH);
        // FFN
        sgemm<<<dim3(2 * HH / BN, NN / BM), tb>>>(outb, ffn_w1, ffn_b1, nullptr, ffn, NN, 2 * HH, HH, 1);
        // h = relu(out + ffn @ w2^T + b2)
        sgemm<<<dim3(HH / BN, NN / BM), tb>>>(ffn, ffn_w2, ffn_b2, outb, h, NN, HH, 2 * HH, 1);
    }

    // head
    sgemm<<<dim3(HH / BN, NN / BM), tb>>>(h, mlp_w1, mlp_b1, nullptr, hid, NN, HH, HH, 1);
    sgemm<<<dim3(NN / BN, NN / BM), tb>>>(hid, mlp_w2, mlp_b2, nullptr, (float*)d_out, NN, NN, HH, 0);
    symmetrize<<<(int)(((long)NN * NN + 255) / 256), 256>>>((float*)d_out, NN);
}

// round 3
// speedup vs baseline: 1.8412x; 1.8412x over previous
#include <cuda_runtime.h>
#include <cuda_bf16.h>
#include <stdint.h>
#include <math.h>

#define NN 4096
#define HH 256
#define EE 65536

// ---------------- device scratch ----------------
__device__ float g_h[NN * HH];
__device__ float g_xlin[NN * HH];
__device__ float g_qkv[NN * 3 * HH];
__device__ float g_attn[NN * HH];
__device__ float g_proj[NN * HH];
__device__ float g_agg[NN * HH];
__device__ float g_out[NN * HH];
__device__ float g_ffn[NN * 2 * HH];
__device__ float g_hid[NN * HH];
__device__ float g_deg[NN];
__device__ float g_dinv[NN];

// ---------------- tf32 helpers ----------------
__device__ __forceinline__ uint32_t f2tf(float f) {
    uint32_t u;
    asm("cvt.rna.tf32.f32 %0, %1;" : "=r"(u) : "f"(f));
    return u;
}

__device__ __forceinline__ void mma_tf32(float c[4], const uint32_t a[4], const uint32_t b[2]) {
    asm volatile(
        "mma.sync.aligned.m16n8k8.row.col.f32.tf32.tf32.f32 "
        "{%0,%1,%2,%3},{%4,%5,%6,%7},{%8,%9},{%0,%1,%2,%3};\n"
        : "+f"(c[0]), "+f"(c[1]), "+f"(c[2]), "+f"(c[3])
        : "r"(a[0]), "r"(a[1]), "r"(a[2]), "r"(a[3]), "r"(b[0]), "r"(b[1]));
}

// ---------------- TF32 tensor-core GEMM ----------------
// C[M,Nn] = act(A[M,K] @ W[Nn,K]^T + bias + add)
// Block: 256 thr = 8 warps (4x2), tile 128x64, BK=16. All dims are multiples.
#define GBM 128
#define GBN 64
#define GBK 16

__global__ void __launch_bounds__(256) tgemm(
    const float* __restrict__ A, const float* __restrict__ W,
    const float* __restrict__ bias, const float* __restrict__ add,
    float* __restrict__ C, int M, int Nn, int K, int relu) {
    __shared__ uint32_t As[GBK][GBM + 8];   // stride 136: conflict-free frag reads
    __shared__ uint32_t Ws[GBK][GBN + 8];   // stride 72

    int tid = threadIdx.x;
    int lane = tid & 31, wid = tid >> 5;
    int warp_m = wid & 3, warp_n = wid >> 2;
    int m0 = blockIdx.y * GBM, n0 = blockIdx.x * GBN;

    float c[2][4][4];
#pragma unroll
    for (int mt = 0; mt < 2; mt++)
#pragma unroll
        for (int nt = 0; nt < 4; nt++)
#pragma unroll
            for (int r = 0; r < 4; r++) c[mt][nt][r] = 0.f;

    for (int k0 = 0; k0 < K; k0 += GBK) {
        // load A tile: 128 rows x 16 k = 512 float4
#pragma unroll
        for (int f = tid; f < 512; f += 256) {
            int row = f >> 2, kc = (f & 3) * 4;
            float4 v = *(const float4*)&A[(long)(m0 + row) * K + k0 + kc];
            As[kc + 0][row] = f2tf(v.x);
            As[kc + 1][row] = f2tf(v.y);
            As[kc + 2][row] = f2tf(v.z);
            As[kc + 3][row] = f2tf(v.w);
        }
        // load W tile: 64 rows x 16 k = 256 float4
        {
            int row = tid >> 2, kc = (tid & 3) * 4;
            float4 v = *(const float4*)&W[(long)(n0 + row) * K + k0 + kc];
            Ws[kc + 0][row] = f2tf(v.x);
            Ws[kc + 1][row] = f2tf(v.y);
            Ws[kc + 2][row] = f2tf(v.z);
            Ws[kc + 3][row] = f2tf(v.w);
        }
        __syncthreads();

#pragma unroll
        for (int ks = 0; ks < GBK; ks += 8) {
            uint32_t a[2][4], b[4][2];
#pragma unroll
            for (int mt = 0; mt < 2; mt++) {
                int row = warp_m * 32 + mt * 16 + (lane >> 2);
                int kk = ks + (lane & 3);
                a[mt][0] = As[kk][row];
                a[mt][1] = As[kk][row + 8];
                a[mt][2] = As[kk + 4][row];
                a[mt][3] = As[kk + 4][row + 8];
            }
#pragma unroll
            for (int nt = 0; nt < 4; nt++) {
                int nc = warp_n * 32 + nt * 8 + (lane >> 2);
                int kk = ks + (lane & 3);
                b[nt][0] = Ws[kk][nc];
                b[nt][1] = Ws[kk + 4][nc];
            }
#pragma unroll
            for (int mt = 0; mt < 2; mt++)
#pragma unroll
                for (int nt = 0; nt < 4; nt++) mma_tf32(c[mt][nt], a[mt], b[nt]);
        }
        __syncthreads();
    }

    // epilogue
#pragma unroll
    for (int mt = 0; mt < 2; mt++) {
        int rb = m0 + warp_m * 32 + mt * 16 + (lane >> 2);
#pragma unroll
        for (int nt = 0; nt < 4; nt++) {
            int cb = n0 + warp_n * 32 + nt * 8 + 2 * (lane & 3);
#pragma unroll
            for (int r = 0; r < 4; r++) {
                int mm = rb + (r >> 1) * 8;
                int nn = cb + (r & 1);
                float v = c[mt][nt][r];
                if (bias) v += bias[nn];
                if (add)  v += add[(long)mm * Nn + nn];
                if (relu) v = fmaxf(v, 0.f);
                C[(long)mm * Nn + nn] = v;
            }
        }
    }
}

// ---------------- TF32 flash attention ----------------
// qkv: [N,768] (q|k|v, each head = 64-ch slice). 128 thr = 4 warps.
// BM=64 (16 rows/warp), BN=64 keys per block, d=64.
// Kd smem is reused for P after the S-matmul.
__global__ void __launch_bounds__(128) flash_tc(const float* __restrict__ qkv,
                                                float* __restrict__ out, int n) {
    __shared__ uint32_t Kd[64][72];   // K^T: [d][key]; later aliased as P: [qrow][key]
    __shared__ uint32_t Vs[64][72];   // V: [key][d]

    int tid = threadIdx.x;
    int lane = tid & 31, wid = tid >> 5;
    int q0 = blockIdx.x * 64;
    int head = blockIdx.y;
    const int C3 = 3 * HH;
    const int qoff = head * 64, koff = HH + head * 64, voff = 2 * HH + head * 64;

    // Q fragments, register-resident (rows 16*wid .. +15), pre-scaled by d^-1/2
    uint32_t qa[8][4];
    {
        int r = q0 + wid * 16 + (lane >> 2);
#pragma unroll
        for (int kt = 0; kt < 8; kt++) {
            int d = kt * 8 + (lane & 3);
            qa[kt][0] = f2tf(qkv[(long)r * C3 + qoff + d] * 0.125f);
            qa[kt][1] = f2tf(qkv[(long)(r + 8) * C3 + qoff + d] * 0.125f);
            qa[kt][2] = f2tf(qkv[(long)r * C3 + qoff + d + 4] * 0.125f);
            qa[kt][3] = f2tf(qkv[(long)(r + 8) * C3 + qoff + d + 4] * 0.125f);
        }
    }

    float m0 = -1e30f, m1 = -1e30f, l0 = 0.f, l1 = 0.f;
    float o[8][4];
#pragma unroll
    for (int nt = 0; nt < 8; nt++)
#pragma unroll
        for (int r = 0; r < 4; r++) o[nt][r] = 0.f;

    for (int k0 = 0; k0 < n; k0 += 64) {
        __syncthreads();   // protect Kd(P)/Vs from previous iteration's readers
        // load K transposed + V: 64 keys x 16 float4 each
#pragma unroll
        for (int f = tid; f < 256; f += 128) {
            int key = f >> 2, dc = (f & 3) * 16;
            const float* kp = &qkv[(long)(k0 + key) * C3 + koff + dc];
            const float* vp = &qkv[(long)(k0 + key) * C3 + voff + dc];
#pragma unroll
            for (int j = 0; j < 16; j += 4) {
                float4 kv = *(const float4*)(kp + j);
                float4 vv = *(const float4*)(vp + j);
                Kd[dc + j + 0][key] = f2tf(kv.x);
                Kd[dc + j + 1][key] = f2tf(kv.y);
                Kd[dc + j + 2][key] = f2tf(kv.z);
                Kd[dc + j + 3][key] = f2tf(kv.w);
                Vs[key][dc + j + 0] = f2tf(vv.x);
                Vs[key][dc + j + 1] = f2tf(vv.y);
                Vs[key][dc + j + 2] = f2tf(vv.z);
                Vs[key][dc + j + 3] = f2tf(vv.w);
            }
        }
        __syncthreads();

        // S = Q K^T   (warp rows 16w..16w+15, all 64 keys)
        float s[8][4];
#pragma unroll
        for (int nt = 0; nt < 8; nt++)
#pragma unroll
            for (int r = 0; r < 4; r++) s[nt][r] = 0.f;
#pragma unroll
        for (int kt = 0; kt < 8; kt++) {
            uint32_t b[2];
            int kk = kt * 8 + (lane & 3);
#pragma unroll
            for (int nt = 0; nt < 8; nt++) {
                int key = nt * 8 + (lane >> 2);
                b[0] = Kd[kk][key];
                b[1] = Kd[kk + 4][key];
                mma_tf32(s[nt], qa[kt], b);
            }
        }

        // online softmax (rows r=lane>>2 and r+8; cols spread over quad)
        float mx0 = -1e30f, mx1 = -1e30f;
#pragma unroll
        for (int nt = 0; nt < 8; nt++) {
            mx0 = fmaxf(mx0, fmaxf(s[nt][0], s[nt][1]));
            mx1 = fmaxf(mx1, fmaxf(s[nt][2], s[nt][3]));
        }
#pragma unroll
        for (int off = 1; off <= 2; off <<= 1) {
            mx0 = fmaxf(mx0, __shfl_xor_sync(0xffffffffu, mx0, off));
            mx1 = fmaxf(mx1, __shfl_xor_sync(0xffffffffu, mx1, off));
        }
        float mn0 = fmaxf(m0, mx0), mn1 = fmaxf(m1, mx1);
        float sum0 = 0.f, sum1 = 0.f;
#pragma unroll
        for (int nt = 0; nt < 8; nt++) {
            s[nt][0] = __expf(s[nt][0] - mn0);
            s[nt][1] = __expf(s[nt][1] - mn0);
            s[nt][2] = __expf(s[nt][2] - mn1);
            s[nt][3] = __expf(s[nt][3] - mn1);
            sum0 += s[nt][0] + s[nt][1];
            sum1 += s[nt][2] + s[nt][3];
        }
#pragma unroll
        for (int off = 1; off <= 2; off <<= 1) {
            sum0 += __shfl_xor_sync(0xffffffffu, sum0, off);
            sum1 += __shfl_xor_sync(0xffffffffu, sum1, off);
        }
        float e0 = __expf(m0 - mn0), e1 = __expf(m1 - mn1);
        l0 = l0 * e0 + sum0;
        l1 = l1 * e1 + sum1;
        m0 = mn0; m1 = mn1;
#pragma unroll
        for (int nt = 0; nt < 8; nt++) {
            o[nt][0] *= e0; o[nt][1] *= e0;
            o[nt][2] *= e1; o[nt][3] *= e1;
        }

        __syncthreads();   // all warps done reading Kd -> safe to overwrite with P

        // write P into Kd region: [qrow][key]
        {
            int r = wid * 16 + (lane >> 2);
#pragma unroll
            for (int nt = 0; nt < 8; nt++) {
                int cb = nt * 8 + 2 * (lane & 3);
                Kd[r][cb]         = f2tf(s[nt][0]);
                Kd[r][cb + 1]     = f2tf(s[nt][1]);
                Kd[r + 8][cb]     = f2tf(s[nt][2]);
                Kd[r + 8][cb + 1] = f2tf(s[nt][3]);
            }
        }
        __syncwarp();   // warp-private rows: warp-level visibility suffices

        // O += P V
#pragma unroll
        for (int kt = 0; kt < 8; kt++) {
            uint32_t a[4];
            int r = wid * 16 + (lane >> 2);
            int kk = kt * 8 + (lane & 3);
            a[0] = Kd[r][kk];
            a[1] = Kd[r + 8][kk];
            a[2] = Kd[r][kk + 4];
            a[3] = Kd[r + 8][kk + 4];
            uint32_t b[2];
#pragma unroll
            for (int nt = 0; nt < 8; nt++) {
                int dd = nt * 8 + (lane >> 2);
                b[0] = Vs[kk][dd];
                b[1] = Vs[kk + 4][dd];
                mma_tf32(o[nt], a, b);
            }
        }
    }

    float inv0 = 1.f / l0, inv1 = 1.f / l1;
    int r = q0 + wid * 16 + (lane >> 2);
#pragma unroll
    for (int nt = 0; nt < 8; nt++) {
        int cb = head * 64 + nt * 8 + 2 * (lane & 3);
        out[(long)r * HH + cb]           = o[nt][0] * inv0;
        out[(long)r * HH + cb + 1]       = o[nt][1] * inv0;
        out[(long)(r + 8) * HH + cb]     = o[nt][2] * inv1;
        out[(long)(r + 8) * HH + cb + 1] = o[nt][3] * inv1;
    }
}

// ---------------- GCN helpers ----------------
__global__ void deg_init(float* deg, int n) {
    int i = blockIdx.x * blockDim.x + threadIdx.x;
    if (i < n) deg[i] = 1.f;
}
__global__ void deg_count(const int* __restrict__ dst, float* deg, int e) {
    int i = blockIdx.x * blockDim.x + threadIdx.x;
    if (i < e) atomicAdd(&deg[dst[i]], 1.f);
}
__global__ void dinv_kernel(const float* __restrict__ deg, float* dinv, int n) {
    int i = blockIdx.x * blockDim.x + threadIdx.x;
    if (i < n) dinv[i] = rsqrtf(deg[i]);
}

__global__ void gcn_scatter(const int* __restrict__ src, const int* __restrict__ dst,
                            const float* __restrict__ dinv, const float* __restrict__ xlin,
                            float* __restrict__ agg, int e) {
    int w = (blockIdx.x * blockDim.x + threadIdx.x) >> 5;
    int lane = threadIdx.x & 31;
    if (w >= e) return;
    int s = src[w], d = dst[w];
    float coef = dinv[s] * dinv[d];
    const float* xs = xlin + (long)s * HH;
    float* ad = agg + (long)d * HH;
#pragma unroll
    for (int k = 0; k < HH / 32; k++)
        atomicAdd(&ad[lane + 32 * k], xs[lane + 32 * k] * coef);
}

__global__ void combine(const float* __restrict__ agg, const float* __restrict__ xlin,
                        const float* __restrict__ dinv, const float* __restrict__ gcn_b,
                        const float* __restrict__ proj, const float* __restrict__ h,
                        float* __restrict__ out, int total) {
    int idx = blockIdx.x * blockDim.x + threadIdx.x;
    if (idx >= total) return;
    int i = idx >> 8, c = idx & 255;
    float dv = dinv[i];
    out[idx] = agg[idx] + xlin[idx] * dv * dv + gcn_b[c] + proj[idx] + 2.f * h[idx];
}

__global__ void symmetrize(float* __restrict__ o, int n) {
    long idx = (long)blockIdx.x * blockDim.x + threadIdx.x;
    if (idx >= (long)n * n) return;
    int i = (int)(idx / n), j = (int)(idx % n);
    if (i < j) {
        long t = (long)j * n + i;
        float v = 0.5f * (o[idx] + o[t]);
        o[idx] = v;
        o[t] = v;
    }
}

// ---------------- launch ----------------
extern "C" void kernel_launch(void* const* d_in, const int* in_sizes, int n_in,
                              void* d_out, int out_size) {
    const float* x      = (const float*)d_in[0];
    const int*   ei     = (const int*)d_in[1];
    const float* pre_w  = (const float*)d_in[2];
    const float* pre_b  = (const float*)d_in[3];
    const float* mlp_w1 = (const float*)d_in[24];
    const float* mlp_b1 = (const float*)d_in[25];
    const float* mlp_w2 = (const float*)d_in[26];
    const float* mlp_b2 = (const float*)d_in[27];

    float *h, *xlin, *qkv, *attn, *proj, *agg, *outb, *ffn, *hid, *deg, *dinv;
    cudaGetSymbolAddress((void**)&h,    g_h);
    cudaGetSymbolAddress((void**)&xlin, g_xlin);
    cudaGetSymbolAddress((void**)&qkv,  g_qkv);
    cudaGetSymbolAddress((void**)&attn, g_attn);
    cudaGetSymbolAddress((void**)&proj, g_proj);
    cudaGetSymbolAddress((void**)&agg,  g_agg);
    cudaGetSymbolAddress((void**)&outb, g_out);
    cudaGetSymbolAddress((void**)&ffn,  g_ffn);
    cudaGetSymbolAddress((void**)&hid,  g_hid);
    cudaGetSymbolAddress((void**)&deg,  g_deg);
    cudaGetSymbolAddress((void**)&dinv, g_dinv);

    // degree / normalization
    deg_init<<<(NN + 255) / 256, 256>>>(deg, NN);
    deg_count<<<(EE + 255) / 256, 256>>>(ei + EE, deg, EE);
    dinv_kernel<<<(NN + 255) / 256, 256>>>(deg, dinv, NN);

    // pre: h = relu(x @ pre_w^T + pre_b)
    tgemm<<<dim3(HH / GBN, NN / GBM), 256>>>(x, pre_w, pre_b, nullptr, h, NN, HH, 128, 1);

    for (int L = 0; L < 2; L++) {
        int base = 4 + L * 10;
        const float* gcn_w  = (const float*)d_in[base + 0];
        const float* gcn_b  = (const float*)d_in[base + 1];
        const float* in_w   = (const float*)d_in[base + 2];
        const float* in_b   = (const float*)d_in[base + 3];
        const float* out_w  = (const float*)d_in[base + 4];
        const float* out_b  = (const float*)d_in[base + 5];
        const float* ffn_w1 = (const float*)d_in[base + 6];
        const float* ffn_b1 = (const float*)d_in[base + 7];
        const float* ffn_w2 = (const float*)d_in[base + 8];
        const float* ffn_b2 = (const float*)d_in[base + 9];

        tgemm<<<dim3(HH / GBN, NN / GBM), 256>>>(h, gcn_w, nullptr, nullptr, xlin, NN, HH, HH, 0);
        tgemm<<<dim3(3 * HH / GBN, NN / GBM), 256>>>(h, in_w, in_b, nullptr, qkv, NN, 3 * HH, HH, 0);
        flash_tc<<<dim3(NN / 64, 4), 128>>>(qkv, attn, NN);
        tgemm<<<dim3(HH / GBN, NN / GBM), 256>>>(attn, out_w, out_b, nullptr, proj, NN, HH, HH, 0);
        cudaMemsetAsync(agg, 0, (size_t)NN * HH * sizeof(float));
        gcn_scatter<<<(EE * 32) / 256, 256>>>(ei, ei + EE, dinv, xlin, agg, EE);
        combine<<<(NN * HH) / 256, 256>>>(agg, xlin, dinv, gcn_b, proj, h, outb, NN * HH);
        tgemm<<<dim3(2 * HH / GBN, NN / GBM), 256>>>(outb, ffn_w1, ffn_b1, nullptr, ffn, NN, 2 * HH, HH, 1);
        tgemm<<<dim3(HH / GBN, NN / GBM), 256>>>(ffn, ffn_w2, ffn_b2, outb, h, NN, HH, 2 * HH, 1);
    }

    // head
    tgemm<<<dim3(HH / GBN, NN / GBM), 256>>>(h, mlp_w1, mlp_b1, nullptr, hid, NN, HH, HH, 1);
    tgemm<<<dim3(NN / GBN, NN / GBM), 256>>>(hid, mlp_w2, mlp_b2, nullptr, (float*)d_out, NN, NN, HH, 0);
    symmetrize<<<(int)(((long)NN * NN + 255) / 256), 256>>>((float*)d_out, NN);
}

// round 4
// speedup vs baseline: 2.4103x; 1.3091x over previous
#include <cuda_runtime.h>
#include <cuda_bf16.h>
#include <stdint.h>
#include <math.h>

#define NN 4096
#define HH 256
#define EE 65536
#define SPLITS 4

// ---------------- device scratch ----------------
__device__ float g_h[NN * HH];
__device__ float g_xlin[NN * HH];
__device__ float g_qkv[NN * 3 * HH];
__device__ float g_attn[NN * HH];
__device__ float g_proj[NN * HH];
__device__ float g_agg[NN * HH];
__device__ float g_out[NN * HH];
__device__ float g_ffn[NN * 2 * HH];
__device__ float g_hid[NN * HH];
__device__ float g_deg[NN];
__device__ float g_dinv[NN];
__device__ float g_opart[SPLITS * NN * HH];
__device__ float g_mpart[SPLITS * 4 * NN];
__device__ float g_lpart[SPLITS * 4 * NN];

// ---------------- helpers ----------------
__device__ __forceinline__ uint32_t f2tf(float f) {
    uint32_t u;
    asm("cvt.rna.tf32.f32 %0, %1;" : "=r"(u) : "f"(f));
    return u;
}

__device__ __forceinline__ void mma_tf32(float c[4], const uint32_t a[4], const uint32_t b[2]) {
    asm volatile(
        "mma.sync.aligned.m16n8k8.row.col.f32.tf32.tf32.f32 "
        "{%0,%1,%2,%3},{%4,%5,%6,%7},{%8,%9},{%0,%1,%2,%3};\n"
        : "+f"(c[0]), "+f"(c[1]), "+f"(c[2]), "+f"(c[3])
        : "r"(a[0]), "r"(a[1]), "r"(a[2]), "r"(a[3]), "r"(b[0]), "r"(b[1]));
}

__device__ __forceinline__ void cpa16(void* s, const void* g) {
    uint32_t sa = (uint32_t)__cvta_generic_to_shared(s);
    asm volatile("cp.async.cg.shared.global [%0], [%1], 16;\n" :: "r"(sa), "l"(g) : "memory");
}
#define CP_COMMIT asm volatile("cp.async.commit_group;\n" ::: "memory")
template<int W> __device__ __forceinline__ void cp_wait() {
    asm volatile("cp.async.wait_group %0;\n" :: "n"(W) : "memory");
}

// ---------------- TF32 GEMM, cp.async double-buffered ----------------
// C[M,Nn] = act(A[M,K] @ W[Nn,K]^T + bias + add). 256 thr = 8 warps (4x2), tile 128x64, BK=16.
#define GBM 128
#define GBN 64
#define GBK 16

__global__ void __launch_bounds__(256) tgemm(
    const float* __restrict__ A, const float* __restrict__ W,
    const float* __restrict__ bias, const float* __restrict__ add,
    float* __restrict__ C, int M, int Nn, int K, int relu) {
    __shared__ float As[2][GBM][20];   // [row][k], stride 20: frag loads conflict-free
    __shared__ float Ws[2][GBN][20];

    int tid = threadIdx.x;
    int lane = tid & 31, wid = tid >> 5;
    int warp_m = wid & 3, warp_n = wid >> 2;
    int m0 = blockIdx.y * GBM, n0 = blockIdx.x * GBN;

    float c[2][4][4];
#pragma unroll
    for (int mt = 0; mt < 2; mt++)
#pragma unroll
        for (int nt = 0; nt < 4; nt++)
#pragma unroll
            for (int r = 0; r < 4; r++) c[mt][nt][r] = 0.f;

    int nIter = K / GBK;

    auto issue = [&](int it, int buf) {
        int k0 = it * GBK;
#pragma unroll
        for (int j = 0; j < 2; j++) {
            int cc = tid + 256 * j;
            int row = cc >> 2, ch = (cc & 3) * 4;
            cpa16(&As[buf][row][ch], &A[(long)(m0 + row) * K + k0 + ch]);
        }
        {
            int row = tid >> 2, ch = (tid & 3) * 4;
            cpa16(&Ws[buf][row][ch], &W[(long)(n0 + row) * K + k0 + ch]);
        }
    };

    issue(0, 0); CP_COMMIT;
    int cur = 0;
    for (int i = 0; i < nIter; i++) {
        if (i + 1 < nIter) { issue(i + 1, cur ^ 1); CP_COMMIT; cp_wait<1>(); }
        else cp_wait<0>();
        __syncthreads();

#pragma unroll
        for (int ks = 0; ks < GBK; ks += 8) {
            uint32_t a[2][4], b[4][2];
            int kk = ks + (lane & 3);
#pragma unroll
            for (int mt = 0; mt < 2; mt++) {
                int row = warp_m * 32 + mt * 16 + (lane >> 2);
                a[mt][0] = f2tf(As[cur][row][kk]);
                a[mt][1] = f2tf(As[cur][row + 8][kk]);
                a[mt][2] = f2tf(As[cur][row][kk + 4]);
                a[mt][3] = f2tf(As[cur][row + 8][kk + 4]);
            }
#pragma unroll
            for (int nt = 0; nt < 4; nt++) {
                int nc = warp_n * 32 + nt * 8 + (lane >> 2);
                b[nt][0] = f2tf(Ws[cur][nc][kk]);
                b[nt][1] = f2tf(Ws[cur][nc][kk + 4]);
            }
#pragma unroll
            for (int mt = 0; mt < 2; mt++)
#pragma unroll
                for (int nt = 0; nt < 4; nt++) mma_tf32(c[mt][nt], a[mt], b[nt]);
        }
        __syncthreads();   // all warps done with buf before next cp.async overwrites it
        cur ^= 1;
    }

    // epilogue
#pragma unroll
    for (int mt = 0; mt < 2; mt++) {
        int rb = m0 + warp_m * 32 + mt * 16 + (lane >> 2);
#pragma unroll
        for (int nt = 0; nt < 4; nt++) {
            int cb = n0 + warp_n * 32 + nt * 8 + 2 * (lane & 3);
#pragma unroll
            for (int r = 0; r < 4; r++) {
                int mm = rb + (r >> 1) * 8;
                int nn = cb + (r & 1);
                float v = c[mt][nt][r];
                if (bias) v += bias[nn];
                if (add)  v += add[(long)mm * Nn + nn];
                if (relu) v = fmaxf(v, 0.f);
                C[(long)mm * Nn + nn] = v;
            }
        }
    }
}

// ---------------- TF32 flash attention, KV-split + cp.async ----------------
// grid (N/64, heads, SPLITS), 128 thr = 4 warps. Each block: 64 q-rows, N/SPLITS keys.
// Emits unnormalized partial acc + (m, l). Kc region aliased for P after S-matmul.
#define KST 68   // K/P smem row stride
#define VST 72   // V smem row stride
#define KBUF (64 * KST)
#define VBUF (64 * VST)

__global__ void __launch_bounds__(128) flash_part(const float* __restrict__ qkv,
                                                  float* __restrict__ opart,
                                                  float* __restrict__ mpart,
                                                  float* __restrict__ lpart) {
    extern __shared__ float sm[];
    float* Ks = sm;                 // [2][64][KST]
    float* Vs = sm + 2 * KBUF;      // [2][64][VST]

    int tid = threadIdx.x;
    int lane = tid & 31, wid = tid >> 5;
    int q0 = blockIdx.x * 64;
    int head = blockIdx.y;
    int split = blockIdx.z;
    const int C3 = 3 * HH;
    const int qoff = head * 64, koff = HH + head * 64, voff = 2 * HH + head * 64;

    // Q fragments (rows 16*wid .. +15), pre-scaled by d^-1/2
    uint32_t qa[8][4];
    {
        int r = q0 + wid * 16 + (lane >> 2);
#pragma unroll
        for (int kt = 0; kt < 8; kt++) {
            int d = kt * 8 + (lane & 3);
            qa[kt][0] = f2tf(qkv[(long)r * C3 + qoff + d] * 0.125f);
            qa[kt][1] = f2tf(qkv[(long)(r + 8) * C3 + qoff + d] * 0.125f);
            qa[kt][2] = f2tf(qkv[(long)r * C3 + qoff + d + 4] * 0.125f);
            qa[kt][3] = f2tf(qkv[(long)(r + 8) * C3 + qoff + d + 4] * 0.125f);
        }
    }

    float m0 = -1e30f, m1 = -1e30f, l0 = 0.f, l1 = 0.f;
    float o[8][4];
#pragma unroll
    for (int nt = 0; nt < 8; nt++)
#pragma unroll
        for (int r = 0; r < 4; r++) o[nt][r] = 0.f;

    int kbase = split * (NN / SPLITS);
    const int nIter = (NN / SPLITS) / 64;   // 16

    auto issue = [&](int it, int buf) {
        int k0 = kbase + it * 64;
#pragma unroll
        for (int j = 0; j < 8; j++) {
            int cc = tid + 128 * j;
            int key = cc >> 4, ch = (cc & 15) * 4;
            cpa16(&Ks[buf * KBUF + key * KST + ch], &qkv[(long)(k0 + key) * C3 + koff + ch]);
            cpa16(&Vs[buf * VBUF + key * VST + ch], &qkv[(long)(k0 + key) * C3 + voff + ch]);
        }
    };

    issue(0, 0); CP_COMMIT;
    int cur = 0;
    for (int i = 0; i < nIter; i++) {
        if (i + 1 < nIter) { issue(i + 1, cur ^ 1); CP_COMMIT; cp_wait<1>(); }
        else cp_wait<0>();
        __syncthreads();

        float* Kc = Ks + cur * KBUF;
        const float* Vc = Vs + cur * VBUF;

        // S = Q K^T
        float s[8][4];
#pragma unroll
        for (int nt = 0; nt < 8; nt++)
#pragma unroll
            for (int r = 0; r < 4; r++) s[nt][r] = 0.f;
#pragma unroll
        for (int kt = 0; kt < 8; kt++) {
            int kk = kt * 8 + (lane & 3);
            uint32_t b[2];
#pragma unroll
            for (int nt = 0; nt < 8; nt++) {
                int key = nt * 8 + (lane >> 2);
                b[0] = f2tf(Kc[key * KST + kk]);
                b[1] = f2tf(Kc[key * KST + kk + 4]);
                mma_tf32(s[nt], qa[kt], b);
            }
        }

        // online softmax (rows r=lane>>2, r+8; cols spread over quad)
        float mx0 = -1e30f, mx1 = -1e30f;
#pragma unroll
        for (int nt = 0; nt < 8; nt++) {
            mx0 = fmaxf(mx0, fmaxf(s[nt][0], s[nt][1]));
            mx1 = fmaxf(mx1, fmaxf(s[nt][2], s[nt][3]));
        }
#pragma unroll
        for (int off = 1; off <= 2; off <<= 1) {
            mx0 = fmaxf(mx0, __shfl_xor_sync(0xffffffffu, mx0, off));
            mx1 = fmaxf(mx1, __shfl_xor_sync(0xffffffffu, mx1, off));
        }
        float mn0 = fmaxf(m0, mx0), mn1 = fmaxf(m1, mx1);
        float sum0 = 0.f, sum1 = 0.f;
#pragma unroll
        for (int nt = 0; nt < 8; nt++) {
            s[nt][0] = __expf(s[nt][0] - mn0);
            s[nt][1] = __expf(s[nt][1] - mn0);
            s[nt][2] = __expf(s[nt][2] - mn1);
            s[nt][3] = __expf(s[nt][3] - mn1);
            sum0 += s[nt][0] + s[nt][1];
            sum1 += s[nt][2] + s[nt][3];
        }
#pragma unroll
        for (int off = 1; off <= 2; off <<= 1) {
            sum0 += __shfl_xor_sync(0xffffffffu, sum0, off);
            sum1 += __shfl_xor_sync(0xffffffffu, sum1, off);
        }
        float e0 = __expf(m0 - mn0), e1 = __expf(m1 - mn1);
        l0 = l0 * e0 + sum0;
        l1 = l1 * e1 + sum1;
        m0 = mn0; m1 = mn1;
#pragma unroll
        for (int nt = 0; nt < 8; nt++) {
            o[nt][0] *= e0; o[nt][1] *= e0;
            o[nt][2] *= e1; o[nt][3] *= e1;
        }

        __syncthreads();   // everyone finished reading Kc -> reuse as P

        // P (tf32 bits) into Kc region: [qrow][key]
        {
            int r = wid * 16 + (lane >> 2);
#pragma unroll
            for (int nt = 0; nt < 8; nt++) {
                int cb = nt * 8 + 2 * (lane & 3);
                Kc[r * KST + cb]           = __uint_as_float(f2tf(s[nt][0]));
                Kc[r * KST + cb + 1]       = __uint_as_float(f2tf(s[nt][1]));
                Kc[(r + 8) * KST + cb]     = __uint_as_float(f2tf(s[nt][2]));
                Kc[(r + 8) * KST + cb + 1] = __uint_as_float(f2tf(s[nt][3]));
            }
        }
        __syncwarp();   // warp-private rows

        // O += P V
#pragma unroll
        for (int kt = 0; kt < 8; kt++) {
            int r = wid * 16 + (lane >> 2);
            int kk = kt * 8 + (lane & 3);
            uint32_t a[4];
            a[0] = __float_as_uint(Kc[r * KST + kk]);
            a[1] = __float_as_uint(Kc[(r + 8) * KST + kk]);
            a[2] = __float_as_uint(Kc[r * KST + kk + 4]);
            a[3] = __float_as_uint(Kc[(r + 8) * KST + kk + 4]);
            uint32_t b[2];
#pragma unroll
            for (int nt = 0; nt < 8; nt++) {
                int dd = nt * 8 + (lane >> 2);
                b[0] = f2tf(Vc[kk * VST + dd]);
                b[1] = f2tf(Vc[(kk + 4) * VST + dd]);
                mma_tf32(o[nt], a, b);
            }
        }
        __syncthreads();   // done with this buf before next cp.async overwrites
        cur ^= 1;
    }

    // unnormalized partials
    int r = q0 + wid * 16 + (lane >> 2);
    float* ob = opart + (long)split * NN * HH;
#pragma unroll
    for (int nt = 0; nt < 8; nt++) {
        int cb = head * 64 + nt * 8 + 2 * (lane & 3);
        ob[(long)r * HH + cb]           = o[nt][0];
        ob[(long)r * HH + cb + 1]       = o[nt][1];
        ob[(long)(r + 8) * HH + cb]     = o[nt][2];
        ob[(long)(r + 8) * HH + cb + 1] = o[nt][3];
    }
    if ((lane & 3) == 0) {
        int base = (split * 4 + head) * NN;
        mpart[base + r] = m0;     lpart[base + r] = l0;
        mpart[base + r + 8] = m1; lpart[base + r + 8] = l1;
    }
}

__global__ void flash_merge(const float* __restrict__ opart, const float* __restrict__ mpart,
                            const float* __restrict__ lpart, float* __restrict__ out) {
    int idx = blockIdx.x * blockDim.x + threadIdx.x;
    if (idx >= NN * HH) return;
    int row = idx >> 8, c = idx & 255, head = c >> 6;
    float mv[SPLITS], lv[SPLITS];
    float mmax = -1e30f;
#pragma unroll
    for (int s = 0; s < SPLITS; s++) {
        mv[s] = mpart[(s * 4 + head) * NN + row];
        lv[s] = lpart[(s * 4 + head) * NN + row];
        mmax = fmaxf(mmax, mv[s]);
    }
    float num = 0.f, den = 0.f;
#pragma unroll
    for (int s = 0; s < SPLITS; s++) {
        float w = __expf(mv[s] - mmax);
        num += opart[(long)s * NN * HH + idx] * w;
        den += lv[s] * w;
    }
    out[idx] = num / den;
}

// ---------------- GCN helpers ----------------
__global__ void deg_init(float* deg, int n) {
    int i = blockIdx.x * blockDim.x + threadIdx.x;
    if (i < n) deg[i] = 1.f;
}
__global__ void deg_count(const int* __restrict__ dst, float* deg, int e) {
    int i = blockIdx.x * blockDim.x + threadIdx.x;
    if (i < e) atomicAdd(&deg[dst[i]], 1.f);
}
__global__ void dinv_kernel(const float* __restrict__ deg, float* dinv, int n) {
    int i = blockIdx.x * blockDim.x + threadIdx.x;
    if (i < n) dinv[i] = rsqrtf(deg[i]);
}

__global__ void gcn_scatter(const int* __restrict__ src, const int* __restrict__ dst,
                            const float* __restrict__ dinv, const float* __restrict__ xlin,
                            float* __restrict__ agg, int e) {
    int w = (blockIdx.x * blockDim.x + threadIdx.x) >> 5;
    int lane = threadIdx.x & 31;
    if (w >= e) return;
    int s = src[w], d = dst[w];
    float coef = dinv[s] * dinv[d];
    const float* xs = xlin + (long)s * HH;
    float* ad = agg + (long)d * HH;
#pragma unroll
    for (int k = 0; k < HH / 32; k++)
        atomicAdd(&ad[lane + 32 * k], xs[lane + 32 * k] * coef);
}

__global__ void combine(const float* __restrict__ agg, const float* __restrict__ xlin,
                        const float* __restrict__ dinv, const float* __restrict__ gcn_b,
                        const float* __restrict__ proj, const float* __restrict__ h,
                        float* __restrict__ out, int total) {
    int idx = blockIdx.x * blockDim.x + threadIdx.x;
    if (idx >= total) return;
    int i = idx >> 8, c = idx & 255;
    float dv = dinv[i];
    out[idx] = agg[idx] + xlin[idx] * dv * dv + gcn_b[c] + proj[idx] + 2.f * h[idx];
}

__global__ void symmetrize(float* __restrict__ o, int n) {
    long idx = (long)blockIdx.x * blockDim.x + threadIdx.x;
    if (idx >= (long)n * n) return;
    int i = (int)(idx / n), j = (int)(idx % n);
    if (i < j) {
        long t = (long)j * n + i;
        float v = 0.5f * (o[idx] + o[t]);
        o[idx] = v;
        o[t] = v;
    }
}

// ---------------- launch ----------------
extern "C" void kernel_launch(void* const* d_in, const int* in_sizes, int n_in,
                              void* d_out, int out_size) {
    const float* x      = (const float*)d_in[0];
    const int*   ei     = (const int*)d_in[1];
    const float* pre_w  = (const float*)d_in[2];
    const float* pre_b  = (const float*)d_in[3];
    const float* mlp_w1 = (const float*)d_in[24];
    const float* mlp_b1 = (const float*)d_in[25];
    const float* mlp_w2 = (const float*)d_in[26];
    const float* mlp_b2 = (const float*)d_in[27];

    float *h, *xlin, *qkv, *attn, *proj, *agg, *outb, *ffn, *hid, *deg, *dinv;
    float *opart, *mpart, *lpart;
    cudaGetSymbolAddress((void**)&h,    g_h);
    cudaGetSymbolAddress((void**)&xlin, g_xlin);
    cudaGetSymbolAddress((void**)&qkv,  g_qkv);
    cudaGetSymbolAddress((void**)&attn, g_attn);
    cudaGetSymbolAddress((void**)&proj, g_proj);
    cudaGetSymbolAddress((void**)&agg,  g_agg);
    cudaGetSymbolAddress((void**)&outb, g_out);
    cudaGetSymbolAddress((void**)&ffn,  g_ffn);
    cudaGetSymbolAddress((void**)&hid,  g_hid);
    cudaGetSymbolAddress((void**)&deg,  g_deg);
    cudaGetSymbolAddress((void**)&dinv, g_dinv);
    cudaGetSymbolAddress((void**)&opart, g_opart);
    cudaGetSymbolAddress((void**)&mpart, g_mpart);
    cudaGetSymbolAddress((void**)&lpart, g_lpart);

    const int flash_smem = (2 * KBUF + 2 * VBUF) * (int)sizeof(float);  // 71680
    cudaFuncSetAttribute(flash_part, cudaFuncAttributeMaxDynamicSharedMemorySize, flash_smem);

    // degree / normalization
    deg_init<<<(NN + 255) / 256, 256>>>(deg, NN);
    deg_count<<<(EE + 255) / 256, 256>>>(ei + EE, deg, EE);
    dinv_kernel<<<(NN + 255) / 256, 256>>>(deg, dinv, NN);

    // pre: h = relu(x @ pre_w^T + pre_b)
    tgemm<<<dim3(HH / GBN, NN / GBM), 256>>>(x, pre_w, pre_b, nullptr, h, NN, HH, 128, 1);

    for (int L = 0; L < 2; L++) {
        int base = 4 + L * 10;
        const float* gcn_w  = (const float*)d_in[base + 0];
        const float* gcn_b  = (const float*)d_in[base + 1];
        const float* in_w   = (const float*)d_in[base + 2];
        const float* in_b   = (const float*)d_in[base + 3];
        const float* out_w  = (const float*)d_in[base + 4];
        const float* out_b  = (const float*)d_in[base + 5];
        const float* ffn_w1 = (const float*)d_in[base + 6];
        const float* ffn_b1 = (const float*)d_in[base + 7];
        const float* ffn_w2 = (const float*)d_in[base + 8];
        const float* ffn_b2 = (const float*)d_in[base + 9];

        tgemm<<<dim3(HH / GBN, NN / GBM), 256>>>(h, gcn_w, nullptr, nullptr, xlin, NN, HH, HH, 0);
        tgemm<<<dim3(3 * HH / GBN, NN / GBM), 256>>>(h, in_w, in_b, nullptr, qkv, NN, 3 * HH, HH, 0);
        flash_part<<<dim3(NN / 64, 4, SPLITS), 128, flash_smem>>>(qkv, opart, mpart, lpart);
        flash_merge<<<(NN * HH) / 256, 256>>>(opart, mpart, lpart, attn);
        tgemm<<<dim3(HH / GBN, NN / GBM), 256>>>(attn, out_w, out_b, nullptr, proj, NN, HH, HH, 0);
        cudaMemsetAsync(agg, 0, (size_t)NN * HH * sizeof(float));
        gcn_scatter<<<(EE * 32) / 256, 256>>>(ei, ei + EE, dinv, xlin, agg, EE);
        combine<<<(NN * HH) / 256, 256>>>(agg, xlin, dinv, gcn_b, proj, h, outb, NN * HH);
        tgemm<<<dim3(2 * HH / GBN, NN / GBM), 256>>>(outb, ffn_w1, ffn_b1, nullptr, ffn, NN, 2 * HH, HH, 1);
        tgemm<<<dim3(HH / GBN, NN / GBM), 256>>>(ffn, ffn_w2, ffn_b2, outb, h, NN, HH, 2 * HH, 1);
    }

    // head
    tgemm<<<dim3(HH / GBN, NN / GBM), 256>>>(h, mlp_w1, mlp_b1, nullptr, hid, NN, HH, HH, 1);
    tgemm<<<dim3(NN / GBN, NN / GBM), 256>>>(hid, mlp_w2, mlp_b2, nullptr, (float*)d_out, NN, NN, HH, 0);
    symmetrize<<<(int)(((long)NN * NN + 255) / 256), 256>>>((float*)d_out, NN);
}

// round 5
// speedup vs baseline: 3.1029x; 1.2874x over previous
#include <cuda_runtime.h>
#include <cuda_bf16.h>
#include <stdint.h>
#include <math.h>

#define NN 4096
#define HH 256
#define EE 65536
#define SPLITS 8

// ---------------- device scratch ----------------
__device__ float g_h[NN * HH];
__device__ float g_xlin[NN * HH];
__device__ float g_qkv[NN * 3 * HH];
__device__ float g_attn[NN * HH];
__device__ float g_proj[NN * HH];
__device__ float g_agg[NN * HH];
__device__ float g_out[NN * HH];
__device__ float g_ffn[NN * 2 * HH];
__device__ float g_hid[NN * HH];
__device__ float g_deg[NN];
__device__ float g_dinv[NN];
__device__ float g_opart[SPLITS * NN * HH];
__device__ float g_mpart[SPLITS * 4 * NN];
__device__ float g_lpart[SPLITS * 4 * NN];

// ---------------- helpers ----------------
__device__ __forceinline__ uint32_t f2tf(float f) {
    uint32_t u;
    asm("cvt.rna.tf32.f32 %0, %1;" : "=r"(u) : "f"(f));
    return u;
}

__device__ __forceinline__ void mma_tf32(float c[4], const uint32_t a[4], const uint32_t b[2]) {
    asm volatile(
        "mma.sync.aligned.m16n8k8.row.col.f32.tf32.tf32.f32 "
        "{%0,%1,%2,%3},{%4,%5,%6,%7},{%8,%9},{%0,%1,%2,%3};\n"
        : "+f"(c[0]), "+f"(c[1]), "+f"(c[2]), "+f"(c[3])
        : "r"(a[0]), "r"(a[1]), "r"(a[2]), "r"(a[3]), "r"(b[0]), "r"(b[1]));
}

__device__ __forceinline__ void cpa16(void* s, const void* g) {
    uint32_t sa = (uint32_t)__cvta_generic_to_shared(s);
    asm volatile("cp.async.cg.shared.global [%0], [%1], 16;\n" :: "r"(sa), "l"(g) : "memory");
}
#define CP_COMMIT asm volatile("cp.async.commit_group;\n" ::: "memory")
template<int W> __device__ __forceinline__ void cp_wait() {
    asm volatile("cp.async.wait_group %0;\n" :: "n"(W) : "memory");
}

// ---------------- TF32 GEMM: 64x64 tile, 4 warps, 3-stage cp.async ----------------
// C[M,Nn] = act(A[M,K] @ W[Nn,K]^T + bias + add)
#define GBK 16

__global__ void __launch_bounds__(128) tgemm(
    const float* __restrict__ A, const float* __restrict__ W,
    const float* __restrict__ bias, const float* __restrict__ add,
    float* __restrict__ C, int M, int Nn, int K, int relu) {
    __shared__ float As[3][64][20];   // stride 20: conflict-free fragment reads
    __shared__ float Ws[3][64][20];

    int tid = threadIdx.x;
    int lane = tid & 31, wid = tid >> 5;
    int warp_m = wid & 1, warp_n = wid >> 1;     // 2x2 warp grid, 32x32 per warp
    int m0 = blockIdx.y * 64, n0 = blockIdx.x * 64;

    float c[2][4][4];
#pragma unroll
    for (int mt = 0; mt < 2; mt++)
#pragma unroll
        for (int nt = 0; nt < 4; nt++)
#pragma unroll
            for (int r = 0; r < 4; r++) c[mt][nt][r] = 0.f;

    int nIter = K / GBK;

    auto issue = [&](int it, int buf) {
        int k0 = it * GBK;
#pragma unroll
        for (int j = 0; j < 2; j++) {
            int cc = tid + 128 * j;
            int row = cc >> 2, ch = (cc & 3) * 4;
            cpa16(&As[buf][row][ch], &A[(long)(m0 + row) * K + k0 + ch]);
            cpa16(&Ws[buf][row][ch], &W[(long)(n0 + row) * K + k0 + ch]);
        }
    };

    issue(0, 0); CP_COMMIT;
    issue(1, 1); CP_COMMIT;

    for (int i = 0; i < nIter; i++) {
        int buf = i % 3;
        if (i + 2 < nIter) { issue(i + 2, (i + 2) % 3); CP_COMMIT; cp_wait<2>(); }
        else if (i + 1 < nIter) cp_wait<1>();
        else cp_wait<0>();
        __syncthreads();

#pragma unroll
        for (int ks = 0; ks < GBK; ks += 8) {
            uint32_t a[2][4], b[4][2];
            int kk = ks + (lane & 3);
#pragma unroll
            for (int mt = 0; mt < 2; mt++) {
                int row = warp_m * 32 + mt * 16 + (lane >> 2);
                a[mt][0] = f2tf(As[buf][row][kk]);
                a[mt][1] = f2tf(As[buf][row + 8][kk]);
                a[mt][2] = f2tf(As[buf][row][kk + 4]);
                a[mt][3] = f2tf(As[buf][row + 8][kk + 4]);
            }
#pragma unroll
            for (int nt = 0; nt < 4; nt++) {
                int nc = warp_n * 32 + nt * 8 + (lane >> 2);
                b[nt][0] = f2tf(Ws[buf][nc][kk]);
                b[nt][1] = f2tf(Ws[buf][nc][kk + 4]);
            }
#pragma unroll
            for (int mt = 0; mt < 2; mt++)
#pragma unroll
                for (int nt = 0; nt < 4; nt++) mma_tf32(c[mt][nt], a[mt], b[nt]);
        }
        __syncthreads();   // protect buf before it is re-issued
    }

    // epilogue
#pragma unroll
    for (int mt = 0; mt < 2; mt++) {
        int rb = m0 + warp_m * 32 + mt * 16 + (lane >> 2);
#pragma unroll
        for (int nt = 0; nt < 4; nt++) {
            int cb = n0 + warp_n * 32 + nt * 8 + 2 * (lane & 3);
#pragma unroll
            for (int r = 0; r < 4; r++) {
                int mm = rb + (r >> 1) * 8;
                int nn = cb + (r & 1);
                float v = c[mt][nt][r];
                if (bias) v += bias[nn];
                if (add)  v += add[(long)mm * Nn + nn];
                if (relu) v = fmaxf(v, 0.f);
                C[(long)mm * Nn + nn] = v;
            }
        }
    }
}

// ---------------- TF32 flash attention, KV-split + cp.async ----------------
// grid (N/64, heads, SPLITS), 128 thr = 4 warps. Each block: 64 q-rows, N/SPLITS keys.
#define KST 68
#define VST 72
#define KBUF (64 * KST)
#define VBUF (64 * VST)

__global__ void __launch_bounds__(128) flash_part(const float* __restrict__ qkv,
                                                  float* __restrict__ opart,
                                                  float* __restrict__ mpart,
                                                  float* __restrict__ lpart) {
    extern __shared__ float sm[];
    float* Ks = sm;                 // [2][64][KST]
    float* Vs = sm + 2 * KBUF;      // [2][64][VST]

    int tid = threadIdx.x;
    int lane = tid & 31, wid = tid >> 5;
    int q0 = blockIdx.x * 64;
    int head = blockIdx.y;
    int split = blockIdx.z;
    const int C3 = 3 * HH;
    const int qoff = head * 64, koff = HH + head * 64, voff = 2 * HH + head * 64;

    uint32_t qa[8][4];
    {
        int r = q0 + wid * 16 + (lane >> 2);
#pragma unroll
        for (int kt = 0; kt < 8; kt++) {
            int d = kt * 8 + (lane & 3);
            qa[kt][0] = f2tf(qkv[(long)r * C3 + qoff + d] * 0.125f);
            qa[kt][1] = f2tf(qkv[(long)(r + 8) * C3 + qoff + d] * 0.125f);
            qa[kt][2] = f2tf(qkv[(long)r * C3 + qoff + d + 4] * 0.125f);
            qa[kt][3] = f2tf(qkv[(long)(r + 8) * C3 + qoff + d + 4] * 0.125f);
        }
    }

    float m0 = -1e30f, m1 = -1e30f, l0 = 0.f, l1 = 0.f;
    float o[8][4];
#pragma unroll
    for (int nt = 0; nt < 8; nt++)
#pragma unroll
        for (int r = 0; r < 4; r++) o[nt][r] = 0.f;

    int kbase = split * (NN / SPLITS);
    const int nIter = (NN / SPLITS) / 64;

    auto issue = [&](int it, int buf) {
        int k0 = kbase + it * 64;
#pragma unroll
        for (int j = 0; j < 8; j++) {
            int cc = tid + 128 * j;
            int key = cc >> 4, ch = (cc & 15) * 4;
            cpa16(&Ks[buf * KBUF + key * KST + ch], &qkv[(long)(k0 + key) * C3 + koff + ch]);
            cpa16(&Vs[buf * VBUF + key * VST + ch], &qkv[(long)(k0 + key) * C3 + voff + ch]);
        }
    };

    issue(0, 0); CP_COMMIT;
    int cur = 0;
    for (int i = 0; i < nIter; i++) {
        if (i + 1 < nIter) { issue(i + 1, cur ^ 1); CP_COMMIT; cp_wait<1>(); }
        else cp_wait<0>();
        __syncthreads();

        float* Kc = Ks + cur * KBUF;
        const float* Vc = Vs + cur * VBUF;

        float s[8][4];
#pragma unroll
        for (int nt = 0; nt < 8; nt++)
#pragma unroll
            for (int r = 0; r < 4; r++) s[nt][r] = 0.f;
#pragma unroll
        for (int kt = 0; kt < 8; kt++) {
            int kk = kt * 8 + (lane & 3);
            uint32_t b[2];
#pragma unroll
            for (int nt = 0; nt < 8; nt++) {
                int key = nt * 8 + (lane >> 2);
                b[0] = f2tf(Kc[key * KST + kk]);
                b[1] = f2tf(Kc[key * KST + kk + 4]);
                mma_tf32(s[nt], qa[kt], b);
            }
        }

        float mx0 = -1e30f, mx1 = -1e30f;
#pragma unroll
        for (int nt = 0; nt < 8; nt++) {
            mx0 = fmaxf(mx0, fmaxf(s[nt][0], s[nt][1]));
            mx1 = fmaxf(mx1, fmaxf(s[nt][2], s[nt][3]));
        }
#pragma unroll
        for (int off = 1; off <= 2; off <<= 1) {
            mx0 = fmaxf(mx0, __shfl_xor_sync(0xffffffffu, mx0, off));
            mx1 = fmaxf(mx1, __shfl_xor_sync(0xffffffffu, mx1, off));
        }
        float mn0 = fmaxf(m0, mx0), mn1 = fmaxf(m1, mx1);
        float sum0 = 0.f, sum1 = 0.f;
#pragma unroll
        for (int nt = 0; nt < 8; nt++) {
            s[nt][0] = __expf(s[nt][0] - mn0);
            s[nt][1] = __expf(s[nt][1] - mn0);
            s[nt][2] = __expf(s[nt][2] - mn1);
            s[nt][3] = __expf(s[nt][3] - mn1);
            sum0 += s[nt][0] + s[nt][1];
            sum1 += s[nt][2] + s[nt][3];
        }
#pragma unroll
        for (int off = 1; off <= 2; off <<= 1) {
            sum0 += __shfl_xor_sync(0xffffffffu, sum0, off);
            sum1 += __shfl_xor_sync(0xffffffffu, sum1, off);
        }
        float e0 = __expf(m0 - mn0), e1 = __expf(m1 - mn1);
        l0 = l0 * e0 + sum0;
        l1 = l1 * e1 + sum1;
        m0 = mn0; m1 = mn1;
#pragma unroll
        for (int nt = 0; nt < 8; nt++) {
            o[nt][0] *= e0; o[nt][1] *= e0;
            o[nt][2] *= e1; o[nt][3] *= e1;
        }

        __syncthreads();   // Kc readers done -> reuse as P

        {
            int r = wid * 16 + (lane >> 2);
#pragma unroll
            for (int nt = 0; nt < 8; nt++) {
                int cb = nt * 8 + 2 * (lane & 3);
                Kc[r * KST + cb]           = __uint_as_float(f2tf(s[nt][0]));
                Kc[r * KST + cb + 1]       = __uint_as_float(f2tf(s[nt][1]));
                Kc[(r + 8) * KST + cb]     = __uint_as_float(f2tf(s[nt][2]));
                Kc[(r + 8) * KST + cb + 1] = __uint_as_float(f2tf(s[nt][3]));
            }
        }
        __syncwarp();

#pragma unroll
        for (int kt = 0; kt < 8; kt++) {
            int r = wid * 16 + (lane >> 2);
            int kk = kt * 8 + (lane & 3);
            uint32_t a[4];
            a[0] = __float_as_uint(Kc[r * KST + kk]);
            a[1] = __float_as_uint(Kc[(r + 8) * KST + kk]);
            a[2] = __float_as_uint(Kc[r * KST + kk + 4]);
            a[3] = __float_as_uint(Kc[(r + 8) * KST + kk + 4]);
            uint32_t b[2];
#pragma unroll
            for (int nt = 0; nt < 8; nt++) {
                int dd = nt * 8 + (lane >> 2);
                b[0] = f2tf(Vc[kk * VST + dd]);
                b[1] = f2tf(Vc[(kk + 4) * VST + dd]);
                mma_tf32(o[nt], a, b);
            }
        }
        __syncthreads();
        cur ^= 1;
    }

    int r = q0 + wid * 16 + (lane >> 2);
    float* ob = opart + (long)split * NN * HH;
#pragma unroll
    for (int nt = 0; nt < 8; nt++) {
        int cb = head * 64 + nt * 8 + 2 * (lane & 3);
        ob[(long)r * HH + cb]           = o[nt][0];
        ob[(long)r * HH + cb + 1]       = o[nt][1];
        ob[(long)(r + 8) * HH + cb]     = o[nt][2];
        ob[(long)(r + 8) * HH + cb + 1] = o[nt][3];
    }
    if ((lane & 3) == 0) {
        int base = (split * 4 + head) * NN;
        mpart[base + r] = m0;     lpart[base + r] = l0;
        mpart[base + r + 8] = m1; lpart[base + r + 8] = l1;
    }
}

__global__ void flash_merge(const float* __restrict__ opart, const float* __restrict__ mpart,
                            const float* __restrict__ lpart, float* __restrict__ out) {
    int idx = blockIdx.x * blockDim.x + threadIdx.x;
    if (idx >= NN * HH) return;
    int row = idx >> 8, c = idx & 255, head = c >> 6;
    float mv[SPLITS], lv[SPLITS];
    float mmax = -1e30f;
#pragma unroll
    for (int s = 0; s < SPLITS; s++) {
        mv[s] = mpart[(s * 4 + head) * NN + row];
        lv[s] = lpart[(s * 4 + head) * NN + row];
        mmax = fmaxf(mmax, mv[s]);
    }
    float num = 0.f, den = 0.f;
#pragma unroll
    for (int s = 0; s < SPLITS; s++) {
        float w = __expf(mv[s] - mmax);
        num += opart[(long)s * NN * HH + idx] * w;
        den += lv[s] * w;
    }
    out[idx] = num / den;
}

// ---------------- GCN helpers ----------------
__global__ void deg_init(float* deg, int n) {
    int i = blockIdx.x * blockDim.x + threadIdx.x;
    if (i < n) deg[i] = 1.f;
}
__global__ void deg_count(const int* __restrict__ dst, float* deg, int e) {
    int i = blockIdx.x * blockDim.x + threadIdx.x;
    if (i < e) atomicAdd(&deg[dst[i]], 1.f);
}
__global__ void dinv_kernel(const float* __restrict__ deg, float* dinv, int n) {
    int i = blockIdx.x * blockDim.x + threadIdx.x;
    if (i < n) dinv[i] = rsqrtf(deg[i]);
}

__global__ void gcn_scatter(const int* __restrict__ src, const int* __restrict__ dst,
                            const float* __restrict__ dinv, const float* __restrict__ xlin,
                            float* __restrict__ agg, int e) {
    int w = (blockIdx.x * blockDim.x + threadIdx.x) >> 5;
    int lane = threadIdx.x & 31;
    if (w >= e) return;
    int s = src[w], d = dst[w];
    float coef = dinv[s] * dinv[d];
    const float* xs = xlin + (long)s * HH;
    float* ad = agg + (long)d * HH;
#pragma unroll
    for (int k = 0; k < HH / 32; k++)
        atomicAdd(&ad[lane + 32 * k], xs[lane + 32 * k] * coef);
}

__global__ void combine(const float* __restrict__ agg, const float* __restrict__ xlin,
                        const float* __restrict__ dinv, const float* __restrict__ gcn_b,
                        const float* __restrict__ proj, const float* __restrict__ h,
                        float* __restrict__ out, int total) {
    int idx = blockIdx.x * blockDim.x + threadIdx.x;
    if (idx >= total) return;
    int i = idx >> 8, c = idx & 255;
    float dv = dinv[i];
    out[idx] = agg[idx] + xlin[idx] * dv * dv + gcn_b[c] + proj[idx] + 2.f * h[idx];
}

// ---------------- tiled symmetrize: (D + D^T)/2 with coalesced transpose ----------------
__global__ void __launch_bounds__(256) symmetrize(float* __restrict__ o) {
    int ti = blockIdx.y, tj = blockIdx.x;
    if (tj < ti) return;
    __shared__ float As[64][65];
    __shared__ float Bs[64][65];
    int tid = threadIdx.x;
    int r = tid >> 2, c0 = (tid & 3) * 16;
    long base_a = (long)ti * 64 * NN + tj * 64;
    long base_b = (long)tj * 64 * NN + ti * 64;

#pragma unroll
    for (int j = 0; j < 16; j += 4) {
        float4 va = *(const float4*)&o[base_a + (long)r * NN + c0 + j];
        float4 vb = *(const float4*)&o[base_b + (long)r * NN + c0 + j];
        As[r][c0 + j] = va.x; As[r][c0 + j + 1] = va.y;
        As[r][c0 + j + 2] = va.z; As[r][c0 + j + 3] = va.w;
        Bs[r][c0 + j] = vb.x; Bs[r][c0 + j + 1] = vb.y;
        Bs[r][c0 + j + 2] = vb.z; Bs[r][c0 + j + 3] = vb.w;
    }
    __syncthreads();

#pragma unroll
    for (int j = 0; j < 16; j += 4) {
        float4 wa, wb;
        wa.x = 0.5f * (As[r][c0 + j]     + Bs[c0 + j][r]);
        wa.y = 0.5f * (As[r][c0 + j + 1] + Bs[c0 + j + 1][r]);
        wa.z = 0.5f * (As[r][c0 + j + 2] + Bs[c0 + j + 2][r]);
        wa.w = 0.5f * (As[r][c0 + j + 3] + Bs[c0 + j + 3][r]);
        *(float4*)&o[base_a + (long)r * NN + c0 + j] = wa;
        if (ti != tj) {
            wb.x = 0.5f * (Bs[r][c0 + j]     + As[c0 + j][r]);
            wb.y = 0.5f * (Bs[r][c0 + j + 1] + As[c0 + j + 1][r]);
            wb.z = 0.5f * (Bs[r][c0 + j + 2] + As[c0 + j + 2][r]);
            wb.w = 0.5f * (Bs[r][c0 + j + 3] + As[c0 + j + 3][r]);
            *(float4*)&o[base_b + (long)r * NN + c0 + j] = wb;
        }
    }
}

// ---------------- launch ----------------
extern "C" void kernel_launch(void* const* d_in, const int* in_sizes, int n_in,
                              void* d_out, int out_size) {
    const float* x      = (const float*)d_in[0];
    const int*   ei     = (const int*)d_in[1];
    const float* pre_w  = (const float*)d_in[2];
    const float* pre_b  = (const float*)d_in[3];
    const float* mlp_w1 = (const float*)d_in[24];
    const float* mlp_b1 = (const float*)d_in[25];
    const float* mlp_w2 = (const float*)d_in[26];
    const float* mlp_b2 = (const float*)d_in[27];

    float *h, *xlin, *qkv, *attn, *proj, *agg, *outb, *ffn, *hid, *deg, *dinv;
    float *opart, *mpart, *lpart;
    cudaGetSymbolAddress((void**)&h,    g_h);
    cudaGetSymbolAddress((void**)&xlin, g_xlin);
    cudaGetSymbolAddress((void**)&qkv,  g_qkv);
    cudaGetSymbolAddress((void**)&attn, g_attn);
    cudaGetSymbolAddress((void**)&proj, g_proj);
    cudaGetSymbolAddress((void**)&agg,  g_agg);
    cudaGetSymbolAddress((void**)&outb, g_out);
    cudaGetSymbolAddress((void**)&ffn,  g_ffn);
    cudaGetSymbolAddress((void**)&hid,  g_hid);
    cudaGetSymbolAddress((void**)&deg,  g_deg);
    cudaGetSymbolAddress((void**)&dinv, g_dinv);
    cudaGetSymbolAddress((void**)&opart, g_opart);
    cudaGetSymbolAddress((void**)&mpart, g_mpart);
    cudaGetSymbolAddress((void**)&lpart, g_lpart);

    const int flash_smem = (2 * KBUF + 2 * VBUF) * (int)sizeof(float);
    cudaFuncSetAttribute(flash_part, cudaFuncAttributeMaxDynamicSharedMemorySize, flash_smem);

    deg_init<<<(NN + 255) / 256, 256>>>(deg, NN);
    deg_count<<<(EE + 255) / 256, 256>>>(ei + EE, deg, EE);
    dinv_kernel<<<(NN + 255) / 256, 256>>>(deg, dinv, NN);

    // pre: h = relu(x @ pre_w^T + pre_b)
    tgemm<<<dim3(HH / 64, NN / 64), 128>>>(x, pre_w, pre_b, nullptr, h, NN, HH, 128, 1);

    for (int L = 0; L < 2; L++) {
        int base = 4 + L * 10;
        const float* gcn_w  = (const float*)d_in[base + 0];
        const float* gcn_b  = (const float*)d_in[base + 1];
        const float* in_w   = (const float*)d_in[base + 2];
        const float* in_b   = (const float*)d_in[base + 3];
        const float* out_w  = (const float*)d_in[base + 4];
        const float* out_b  = (const float*)d_in[base + 5];
        const float* ffn_w1 = (const float*)d_in[base + 6];
        const float* ffn_b1 = (const float*)d_in[base + 7];
        const float* ffn_w2 = (const float*)d_in[base + 8];
        const float* ffn_b2 = (const float*)d_in[base + 9];

        tgemm<<<dim3(HH / 64, NN / 64), 128>>>(h, gcn_w, nullptr, nullptr, xlin, NN, HH, HH, 0);
        tgemm<<<dim3(3 * HH / 64, NN / 64), 128>>>(h, in_w, in_b, nullptr, qkv, NN, 3 * HH, HH, 0);
        flash_part<<<dim3(NN / 64, 4, SPLITS), 128, flash_smem>>>(qkv, opart, mpart, lpart);
        flash_merge<<<(NN * HH) / 256, 256>>>(opart, mpart, lpart, attn);
        tgemm<<<dim3(HH / 64, NN / 64), 128>>>(attn, out_w, out_b, nullptr, proj, NN, HH, HH, 0);
        cudaMemsetAsync(agg, 0, (size_t)NN * HH * sizeof(float));
        gcn_scatter<<<(EE * 32) / 256, 256>>>(ei, ei + EE, dinv, xlin, agg, EE);
        combine<<<(NN * HH) / 256, 256>>>(agg, xlin, dinv, gcn_b, proj, h, outb, NN * HH);
        tgemm<<<dim3(2 * HH / 64, NN / 64), 128>>>(outb, ffn_w1, ffn_b1, nullptr, ffn, NN, 2 * HH, HH, 1);
        tgemm<<<dim3(HH / 64, NN / 64), 128>>>(ffn, ffn_w2, ffn_b2, outb, h, NN, HH, 2 * HH, 1);
    }

    // head
    tgemm<<<dim3(HH / 64, NN / 64), 128>>>(h, mlp_w1, mlp_b1, nullptr, hid, NN, HH, HH, 1);
    tgemm<<<dim3(NN / 64, NN / 64), 128>>>(hid, mlp_w2, mlp_b2, nullptr, (float*)d_out, NN, NN, HH, 0);
    symmetrize<<<dim3(NN / 64, NN / 64), 256>>>((float*)d_out);
}